// round 14
// baseline (speedup 1.0000x reference)
#include <cuda_runtime.h>
#include <cuda_fp16.h>
#include <cstdint>

// Problem constants (fixed by setup_inputs)
#define BMAX 16384
#define NROWS_MAX (BMAX * 5)

// ============================================================================
// Scratch (__device__ globals; no allocation allowed)
//   Pure fp16 scheme: activations AND weights single fp16.
// ============================================================================
__device__ __half g_inp[(size_t)NROWS_MAX * 160];   // 26 MB
__device__ __half g_h[(size_t)NROWS_MAX * 512];     // 84 MB
__device__ __half g_w1t[512 * 160];
__device__ __half g_w2t[512 * 256];

// ============================================================================
// Warp-MMA + cp.async helpers (sm_80-era PTX: legal on compute_103)
// ============================================================================
#define LDSM_X4(r0, r1, r2, r3, addr) \
    asm volatile("ldmatrix.sync.aligned.m8n8.x4.shared.b16 {%0,%1,%2,%3}, [%4];" \
        : "=r"(r0), "=r"(r1), "=r"(r2), "=r"(r3) : "r"(addr))

__device__ __forceinline__ void mma16816(float* d, const uint32_t* a, const uint32_t* b) {
    asm volatile(
        "mma.sync.aligned.m16n8k16.row.col.f32.f16.f16.f32 "
        "{%0,%1,%2,%3}, {%4,%5,%6,%7}, {%8,%9}, {%0,%1,%2,%3};"
        : "+f"(d[0]), "+f"(d[1]), "+f"(d[2]), "+f"(d[3])
        : "r"(a[0]), "r"(a[1]), "r"(a[2]), "r"(a[3]), "r"(b[0]), "r"(b[1]));
}

__device__ __forceinline__ uint32_t smem_u32(const void* p) {
    uint32_t a;
    asm("{ .reg .u64 tmp; cvta.to.shared.u64 tmp, %1; cvt.u32.u64 %0, tmp; }"
        : "=r"(a) : "l"(p));
    return a;
}

#define CP_ASYNC16(dst, src) \
    asm volatile("cp.async.ca.shared.global [%0], [%1], 16;" :: "r"(dst), "l"(src))
#define CP_COMMIT() asm volatile("cp.async.commit_group;" ::: "memory")
#define CP_WAIT(n)  asm volatile("cp.async.wait_group %0;" :: "n"(n) : "memory")

// Stage a 128-row x 32-col fp16 tile into smem (80B row stride), 256 threads.
__device__ __forceinline__ void stage128x32_t256(
    uint32_t sdst, const __half* __restrict__ gsrc, int gstride, int t)
{
#pragma unroll
    for (int i = 0; i < 2; i++) {
        int idx = t + i * 256;
        int row = idx >> 2, q = idx & 3;
        CP_ASYNC16(sdst + row * 80 + q * 16, gsrc + (size_t)row * gstride + q * 8);
    }
}

// ---------------------------------------------------------------------------
// K-edge (factored SIMT) + fused prep. Writes g_inp (fp16 single).
// ---------------------------------------------------------------------------
__global__ __launch_bounds__(256) void k_edge(
    const float* __restrict__ obs, const float* __restrict__ act,
    const float* __restrict__ ag,  const float* __restrict__ g,
    const float* __restrict__ mp_w, const float* __restrict__ mp_b)
{
    extern __shared__ float smem[];
    float* sw   = smem;              // 46*128
    float* sinp = smem + 46 * 128;   // 8*132
    const int t  = threadIdx.x;
    const int b0 = blockIdx.x * 8;

    for (int i = t; i < 46 * 128; i += 256) sw[i] = mp_w[i];

    for (int idx = t; idx < 8 * 129; idx += 256) {
        int bl = idx / 129;
        int j  = idx - bl * 129;
        int b  = b0 + bl;
        float v;
        if (j < 10)       v = obs[b * 85 + j];
        else if (j < 14)  v = act[b * 4 + (j - 10)];
        else if (j < 54) {
            int e = (j - 14) >> 1;
            int w = (j - 14) & 1;
            v = g[b * 30 + e + w * 10] - ag[b * 30 + e + w * 10];
        } else {
            v = obs[b * 85 + 10 + (j - 54)];
        }
        sinp[bl * 132 + j] = v;
    }
    __syncthreads();

    const int nb = t & 31;
    const int bl = t >> 5;
    const int n0 = nb * 4;
    const float4* sw4 = reinterpret_cast<const float4*>(sw);
    const float* ip = sinp + bl * 132;

    float4 tb = *reinterpret_cast<const float4*>(mp_b + n0);
#pragma unroll
    for (int k = 0; k < 14; k++) {
        float  a = ip[k];
        float4 w = sw4[k * 32 + nb];
        tb.x += a * w.x; tb.y += a * w.y; tb.z += a * w.z; tb.w += a * w.w;
    }

    float ts[5][4], td[5][4];
#pragma unroll
    for (int n = 0; n < 5; n++)
#pragma unroll
        for (int c = 0; c < 4; c++) { ts[n][c] = 0.0f; td[n][c] = 0.0f; }

#pragma unroll
    for (int k = 0; k < 15; k++) {
        float4 ws = sw4[(16 + k) * 32 + nb];
        float4 wd = sw4[(31 + k) * 32 + nb];
#pragma unroll
        for (int n = 0; n < 5; n++) {
            float a = ip[54 + n * 15 + k];
            ts[n][0] += a * ws.x; ts[n][1] += a * ws.y;
            ts[n][2] += a * ws.z; ts[n][3] += a * ws.w;
            td[n][0] += a * wd.x; td[n][1] += a * wd.y;
            td[n][2] += a * wd.z; td[n][3] += a * wd.w;
        }
    }

    const float4 w14 = sw4[14 * 32 + nb];
    const float4 w15 = sw4[15 * 32 + nb];

    float acc[5][4];
#pragma unroll
    for (int i = 0; i < 5; i++)
#pragma unroll
        for (int c = 0; c < 4; c++) acc[i][c] = 0.0f;

#pragma unroll
    for (int e = 0; e < 20; e++) {
        const int src = e >> 2, rr = e & 3;
        const int dst = (rr < src) ? rr : rr + 1;
        float d0 = ip[14 + e * 2];
        float d1 = ip[15 + e * 2];
        float v0 = tb.x + ts[src][0] + td[dst][0] + d0 * w14.x + d1 * w15.x;
        float v1 = tb.y + ts[src][1] + td[dst][1] + d0 * w14.y + d1 * w15.y;
        float v2 = tb.z + ts[src][2] + td[dst][2] + d0 * w14.z + d1 * w15.z;
        float v3 = tb.w + ts[src][3] + td[dst][3] + d0 * w14.w + d1 * w15.w;
        acc[dst][0] += fmaxf(v0, 0.0f);
        acc[dst][1] += fmaxf(v1, 0.0f);
        acc[dst][2] += fmaxf(v2, 0.0f);
        acc[dst][3] += fmaxf(v3, 0.0f);
    }

    const int b = b0 + bl;
#pragma unroll
    for (int i = 0; i < 5; i++) {
        size_t base = (size_t)(b * 5 + i) * 160 + 29 + n0;
#pragma unroll
        for (int c = 0; c < 4; c++)
            g_inp[base + c] = __float2half_rn(acc[i][c]);
    }

    // fused prep: cols 0..28 + zero 157..159, straight from sinp
    for (int idx = t; idx < 8 * 5 * 32; idx += 256) {
        int rl = idx >> 5;
        int c  = idx & 31;
        int bl2 = rl / 5;
        int n   = rl - bl2 * 5;
        const float* ip2 = sinp + bl2 * 132;
        float v; int col;
        if (c < 4)       { v = ip2[10 + c];                 col = c; }
        else if (c < 14) { v = ip2[c - 4];                  col = c; }
        else if (c < 29) { v = ip2[54 + n * 15 + (c - 14)]; col = c; }
        else             { v = 0.0f;                         col = 128 + c; }
        size_t off = (size_t)((b0 + bl2) * 5 + n) * 160 + col;
        g_inp[off] = __float2half_rn(v);
    }
}

// ---------------------------------------------------------------------------
// K-wconv (+ fused out init): transpose weights to fp16.
// ---------------------------------------------------------------------------
__global__ void k_wconv(const float* __restrict__ w1, const float* __restrict__ w3,
                        const float* __restrict__ w2, const float* __restrict__ w4,
                        float* __restrict__ out,
                        const float* __restrict__ rb1, const float* __restrict__ rb2,
                        int B)
{
    int idx = blockIdx.x * 256 + threadIdx.x;
    const int N1 = 512 * 160;
    const int N2 = 512 * 256;
    if (idx < N1) {
        int n = idx / 160, k = idx - n * 160;
        float v = 0.0f;
        if (k < 157) v = (n < 256) ? w1[k * 256 + n] : w3[k * 256 + (n - 256)];
        g_w1t[idx] = __float2half_rn(v);
    } else if (idx < N1 + N2) {
        int j = idx - N1;
        int n = j / 256, k = j - n * 256;
        float v = (n < 256) ? w2[k * 256 + n] : w4[k * 256 + (n - 256)];
        g_w2t[j] = __float2half_rn(v);
    }
    if (idx < B) { out[idx] = rb1[0]; out[B + idx] = rb2[0]; }
}

// ---------------------------------------------------------------------------
// Pipeline layout: bias 0..512, rho 512..1024, s_arr 1024..1536,
// 2 buffers x { A, B } each 128x80B = 10240B. Total 42496; 2 CTAs/SM.
// Warp layout: 2(M) x 4(N); warp tile m64 x n32.
// ---------------------------------------------------------------------------
#define PP_BIAS  0
#define PP_RHO   512
#define PP_SARR  1024
#define PP_BUF   1536
#define PP_TILE  10240
#define PP_BUFSZ (2 * PP_TILE)           // 20480
#define PP_SMEM  (PP_BUF + 2 * PP_BUFSZ) // 42496

// single-term fp16 compute, 2Mx4N: D += A*B
#define CHUNK_COMPUTE(bb)                                                       \
    do {                                                                        \
        const uint32_t base_ = sbase + PP_BUF + (bb) * PP_BUFSZ;                \
        _Pragma("unroll")                                                       \
        for (int ks = 0; ks < 2; ks++) {                                        \
            const uint32_t a_off = (uint32_t)(a_row * 80 + (ks * 16 + a_ksub) * 2); \
            const uint32_t b_off = (uint32_t)(b_row * 80 + (ks * 16 + b_ksub) * 2); \
            uint32_t af[4][4];                                                  \
            _Pragma("unroll")                                                   \
            for (int mt = 0; mt < 4; mt++)                                      \
                LDSM_X4(af[mt][0], af[mt][1], af[mt][2], af[mt][3],             \
                        base_ + a_off + mt * 16 * 80);                          \
            _Pragma("unroll")                                                   \
            for (int p = 0; p < 2; p++) {                                       \
                uint32_t bh[4];                                                 \
                LDSM_X4(bh[0], bh[1], bh[2], bh[3],                             \
                        base_ + PP_TILE + b_off + p * 16 * 80);                 \
                _Pragma("unroll")                                               \
                for (int mt = 0; mt < 4; mt++)                                  \
                    _Pragma("unroll")                                           \
                    for (int hh = 0; hh < 2; hh++)                              \
                        mma16816(acc[mt][p * 2 + hh], af[mt], &bh[hh * 2]);     \
            }                                                                   \
        }                                                                       \
    } while (0)

#define STAGE_CHUNK(bb, kc)                                                     \
    do {                                                                        \
        uint32_t sd_ = sbase + PP_BUF + (bb) * PP_BUFSZ;                        \
        stage128x32_t256(sd_,            A_src + (kc) * 32, a_stride, t);       \
        stage128x32_t256(sd_ + PP_TILE,  B_src + (kc) * 32, b_stride, t);       \
        CP_COMMIT();                                                            \
    } while (0)

// ---------------------------------------------------------------------------
// K-phi1 (MMA, fp16, pipelined, 2Mx4N): K=160, 5 chunks of 32.
// grid (4 nc, nrows/128): nc-CTAs sharing an A-tile are launch-adjacent (L2).
// ---------------------------------------------------------------------------
__global__ __launch_bounds__(256, 2) void k_phi1_mma(
    const float* __restrict__ phi_b1, const float* __restrict__ phi_b3)
{
    extern __shared__ char smemc[];
    const uint32_t sbase = smem_u32(smemc);
    const int t    = threadIdx.x;
    const int wid  = t >> 5;
    const int lane = t & 31;
    const int nc   = blockIdx.x;            // which 128 of N=512
    const int m0   = blockIdx.y * 128;

    float* sb = reinterpret_cast<float*>(smemc + PP_BIAS);
    if (t < 128) {
        int n = nc * 128 + t;
        sb[t] = (n < 256) ? phi_b1[n] : phi_b3[n - 256];
    }

    const __half* A_src = g_inp + (size_t)m0 * 160;
    const __half* B_src = g_w1t + (size_t)(nc * 128) * 160;
    const int a_stride = 160, b_stride = 160;

    const int warp_m = wid & 1;    // 2 x 64 rows
    const int warp_n = wid >> 1;   // 4 x 32 cols

    float acc[4][4][4];
#pragma unroll
    for (int mt = 0; mt < 4; mt++)
#pragma unroll
        for (int nt = 0; nt < 4; nt++)
#pragma unroll
            for (int j = 0; j < 4; j++) acc[mt][nt][j] = 0.0f;

    const int a_row  = warp_m * 64 + (lane & 15);
    const int a_ksub = (lane >> 4) * 8;
    const int b_row  = warp_n * 32 + (lane & 7) + ((lane >> 4) & 1) * 8;
    const int b_ksub = ((lane >> 3) & 1) * 8;

    STAGE_CHUNK(0, 0);
#pragma unroll
    for (int kc = 0; kc < 5; kc++) {
        if (kc < 4) {
            STAGE_CHUNK((kc + 1) & 1, kc + 1);
            CP_WAIT(1);
        } else {
            CP_WAIT(0);
        }
        __syncthreads();
        CHUNK_COMPUTE(kc & 1);
        __syncthreads();
    }

    // epilogue: relu(+bias) -> g_h (fp16)
#pragma unroll
    for (int mt = 0; mt < 4; mt++)
#pragma unroll
        for (int nt = 0; nt < 4; nt++) {
            int c = warp_n * 32 + nt * 8 + (lane & 3) * 2;
            float b0 = sb[c], b1 = sb[c + 1];
#pragma unroll
            for (int half_i = 0; half_i < 2; half_i++) {
                int row = warp_m * 64 + mt * 16 + (lane >> 2) + half_i * 8;
                float v0 = fmaxf(acc[mt][nt][half_i * 2]     + b0, 0.0f);
                float v1 = fmaxf(acc[mt][nt][half_i * 2 + 1] + b1, 0.0f);
                __half h0 = __float2half_rn(v0);
                __half h1 = __float2half_rn(v1);
                uint32_t ph = ((uint32_t)__half_as_ushort(h1) << 16) | __half_as_ushort(h0);
                size_t off = (size_t)(m0 + row) * 512 + nc * 128 + c;
                *reinterpret_cast<uint32_t*>(g_h + off) = ph;
            }
        }
}

// ---------------------------------------------------------------------------
// K-phi2 (MMA, fp16, pipelined, 2Mx4N): K=256, 8 chunks of 32.
// grid (4, nrows/128): x = br*2+nc -> A-tile-sharing pair launch-adjacent (L2).
// ---------------------------------------------------------------------------
__global__ __launch_bounds__(256, 2) void k_phi2_mma(
    const float* __restrict__ phi_b2, const float* __restrict__ phi_b4,
    const float* __restrict__ rho_w1, const float* __restrict__ rho_w2,
    float* __restrict__ out, int B)
{
    extern __shared__ char smemc[];
    const uint32_t sbase = smem_u32(smemc);
    const int t    = threadIdx.x;
    const int wid  = t >> 5;
    const int lane = t & 31;
    const int br   = blockIdx.x >> 1;
    const int nc   = blockIdx.x & 1;
    const int m0   = blockIdx.y * 128;

    const float* bias = br ? phi_b4 : phi_b2;
    const float* rho  = br ? rho_w2 : rho_w1;

    float* sb    = reinterpret_cast<float*>(smemc + PP_BIAS);
    float* sr    = reinterpret_cast<float*>(smemc + PP_RHO);
    float* s_arr = reinterpret_cast<float*>(smemc + PP_SARR);

    if (t < 128) {
        sb[t] = bias[nc * 128 + t];
        sr[t] = rho[nc * 128 + t];
        s_arr[t] = 0.0f;
    }

    const __half* A_src = g_h + (size_t)m0 * 512 + br * 256;
    const __half* B_src = g_w2t + (size_t)(br * 256 + nc * 128) * 256;
    const int a_stride = 512, b_stride = 256;

    const int warp_m = wid & 1;    // 2 x 64 rows
    const int warp_n = wid >> 1;   // 4 x 32 cols

    float acc[4][4][4];
#pragma unroll
    for (int mt = 0; mt < 4; mt++)
#pragma unroll
        for (int nt = 0; nt < 4; nt++)
#pragma unroll
            for (int j = 0; j < 4; j++) acc[mt][nt][j] = 0.0f;

    const int a_row  = warp_m * 64 + (lane & 15);
    const int a_ksub = (lane >> 4) * 8;
    const int b_row  = warp_n * 32 + (lane & 7) + ((lane >> 4) & 1) * 8;
    const int b_ksub = ((lane >> 3) & 1) * 8;

    STAGE_CHUNK(0, 0);
#pragma unroll
    for (int kc = 0; kc < 8; kc++) {
        if (kc < 7) {
            STAGE_CHUNK((kc + 1) & 1, kc + 1);
            CP_WAIT(1);
        } else {
            CP_WAIT(0);
        }
        __syncthreads();
        CHUNK_COMPUTE(kc & 1);
        __syncthreads();
    }

    // epilogue: relu(+bias)*rho, reduce cols, per-row sums, per-b atomics
#pragma unroll
    for (int mt = 0; mt < 4; mt++) {
        float s0 = 0.0f, s1 = 0.0f;
#pragma unroll
        for (int nt = 0; nt < 4; nt++) {
            int c = warp_n * 32 + nt * 8 + (lane & 3) * 2;
            float b0v = sb[c], b1v = sb[c + 1];
            float r0v = sr[c], r1v = sr[c + 1];
            s0 += fmaxf(acc[mt][nt][0] + b0v, 0.0f) * r0v;
            s0 += fmaxf(acc[mt][nt][1] + b1v, 0.0f) * r1v;
            s1 += fmaxf(acc[mt][nt][2] + b0v, 0.0f) * r0v;
            s1 += fmaxf(acc[mt][nt][3] + b1v, 0.0f) * r1v;
        }
        s0 += __shfl_xor_sync(0xffffffffu, s0, 1);
        s0 += __shfl_xor_sync(0xffffffffu, s0, 2);
        s1 += __shfl_xor_sync(0xffffffffu, s1, 1);
        s1 += __shfl_xor_sync(0xffffffffu, s1, 2);
        if ((lane & 3) == 0) {
            int row = warp_m * 64 + mt * 16 + (lane >> 2);
            atomicAdd(&s_arr[row], s0);
            atomicAdd(&s_arr[row + 8], s1);
        }
    }
    __syncthreads();

    {
        int bfirst = m0 / 5;
        int blast  = (m0 + 127) / 5;
        int ng = blast - bfirst + 1;
        if (t < ng) {
            int b = bfirst + t;
            float s = 0.0f;
#pragma unroll
            for (int r = 0; r < 5; r++) {
                int m = b * 5 + r;
                if (m >= m0 && m < m0 + 128) s += s_arr[m - m0];
            }
            atomicAdd(&out[br * B + b], s);
        }
    }
}

// ---------------------------------------------------------------------------
extern "C" void kernel_launch(void* const* d_in, const int* in_sizes, int n_in,
                              void* d_out, int out_size)
{
    const float* obs    = (const float*)d_in[0];
    const float* act    = (const float*)d_in[1];
    const float* ag     = (const float*)d_in[2];
    const float* g      = (const float*)d_in[3];
    const float* mp_w   = (const float*)d_in[4];
    const float* mp_b   = (const float*)d_in[5];
    const float* phi_w1 = (const float*)d_in[6];
    const float* phi_b1 = (const float*)d_in[7];
    const float* phi_w2 = (const float*)d_in[8];
    const float* phi_b2 = (const float*)d_in[9];
    const float* phi_w3 = (const float*)d_in[10];
    const float* phi_b3 = (const float*)d_in[11];
    const float* phi_w4 = (const float*)d_in[12];
    const float* phi_b4 = (const float*)d_in[13];
    const float* rho_w1 = (const float*)d_in[14];
    const float* rho_b1 = (const float*)d_in[15];
    const float* rho_w2 = (const float*)d_in[16];
    const float* rho_b2 = (const float*)d_in[17];
    float* out = (float*)d_out;

    const int B = in_sizes[1] / 4;  // act is (B,4)
    const int nrows = B * 5;

    const int S1 = (46 * 128 + 8 * 132) * 4;   // 27,776 B
    cudaFuncSetAttribute(k_edge, cudaFuncAttributeMaxDynamicSharedMemorySize, S1);
    cudaFuncSetAttribute(k_phi1_mma, cudaFuncAttributeMaxDynamicSharedMemorySize, PP_SMEM);
    cudaFuncSetAttribute(k_phi2_mma, cudaFuncAttributeMaxDynamicSharedMemorySize, PP_SMEM);

    k_wconv<<<(512 * 160 + 512 * 256 + 255) / 256, 256>>>(
        phi_w1, phi_w3, phi_w2, phi_w4, out, rho_b1, rho_b2, B);
    k_edge<<<B / 8, 256, S1>>>(obs, act, ag, g, mp_w, mp_b);
    k_phi1_mma<<<dim3(4, nrows / 128), 256, PP_SMEM>>>(phi_b1, phi_b3);
    k_phi2_mma<<<dim3(4, nrows / 128), 256, PP_SMEM>>>(
        phi_b2, phi_b4, rho_w1, rho_w2, out, B);
}

// round 15
// speedup vs baseline: 1.3489x; 1.3489x over previous
#include <cuda_runtime.h>
#include <cuda_fp16.h>
#include <cstdint>

// Problem constants (fixed by setup_inputs)
#define BMAX 16384
#define NROWS_MAX (BMAX * 5)

// ============================================================================
// Scratch (__device__ globals; no allocation allowed)
//   Pure fp16 scheme. g_inp padded K: 192 (cols 157..191 zero).
// ============================================================================
__device__ __half g_inp[(size_t)NROWS_MAX * 192];   // 31 MB
__device__ __half g_h[(size_t)NROWS_MAX * 512];     // 84 MB
__device__ __half g_w1t[512 * 192];
__device__ __half g_w2t[512 * 256];

// ============================================================================
// Warp-MMA + cp.async helpers (sm_80-era PTX: legal on compute_103)
// ============================================================================
#define LDSM_X4(r0, r1, r2, r3, addr) \
    asm volatile("ldmatrix.sync.aligned.m8n8.x4.shared.b16 {%0,%1,%2,%3}, [%4];" \
        : "=r"(r0), "=r"(r1), "=r"(r2), "=r"(r3) : "r"(addr))

__device__ __forceinline__ void mma16816(float* d, const uint32_t* a, const uint32_t* b) {
    asm volatile(
        "mma.sync.aligned.m16n8k16.row.col.f32.f16.f16.f32 "
        "{%0,%1,%2,%3}, {%4,%5,%6,%7}, {%8,%9}, {%0,%1,%2,%3};"
        : "+f"(d[0]), "+f"(d[1]), "+f"(d[2]), "+f"(d[3])
        : "r"(a[0]), "r"(a[1]), "r"(a[2]), "r"(a[3]), "r"(b[0]), "r"(b[1]));
}

__device__ __forceinline__ uint32_t smem_u32(const void* p) {
    uint32_t a;
    asm("{ .reg .u64 tmp; cvta.to.shared.u64 tmp, %1; cvt.u32.u64 %0, tmp; }"
        : "=r"(a) : "l"(p));
    return a;
}

#define CP_ASYNC16(dst, src) \
    asm volatile("cp.async.ca.shared.global [%0], [%1], 16;" :: "r"(dst), "l"(src))
#define CP_COMMIT() asm volatile("cp.async.commit_group;" ::: "memory")
#define CP_WAIT(n)  asm volatile("cp.async.wait_group %0;" :: "n"(n) : "memory")

// Stage a 128-row x 64-col fp16 tile into smem (144B row stride), 256 threads.
__device__ __forceinline__ void stage128x64_t256(
    uint32_t sdst, const __half* __restrict__ gsrc, int gstride, int t)
{
#pragma unroll
    for (int i = 0; i < 4; i++) {
        int idx = t + i * 256;
        int row = idx >> 3, q = idx & 7;
        CP_ASYNC16(sdst + row * 144 + q * 16, gsrc + (size_t)row * gstride + q * 8);
    }
}

// ---------------------------------------------------------------------------
// K-edge (factored SIMT) + fused prep. Writes g_inp (fp16, stride 192).
// ---------------------------------------------------------------------------
__global__ __launch_bounds__(256) void k_edge(
    const float* __restrict__ obs, const float* __restrict__ act,
    const float* __restrict__ ag,  const float* __restrict__ g,
    const float* __restrict__ mp_w, const float* __restrict__ mp_b)
{
    extern __shared__ float smem[];
    float* sw   = smem;              // 46*128
    float* sinp = smem + 46 * 128;   // 8*132
    const int t  = threadIdx.x;
    const int b0 = blockIdx.x * 8;

    for (int i = t; i < 46 * 128; i += 256) sw[i] = mp_w[i];

    for (int idx = t; idx < 8 * 129; idx += 256) {
        int bl = idx / 129;
        int j  = idx - bl * 129;
        int b  = b0 + bl;
        float v;
        if (j < 10)       v = obs[b * 85 + j];
        else if (j < 14)  v = act[b * 4 + (j - 10)];
        else if (j < 54) {
            int e = (j - 14) >> 1;
            int w = (j - 14) & 1;
            v = g[b * 30 + e + w * 10] - ag[b * 30 + e + w * 10];
        } else {
            v = obs[b * 85 + 10 + (j - 54)];
        }
        sinp[bl * 132 + j] = v;
    }
    __syncthreads();

    const int nb = t & 31;
    const int bl = t >> 5;
    const int n0 = nb * 4;
    const float4* sw4 = reinterpret_cast<const float4*>(sw);
    const float* ip = sinp + bl * 132;

    float4 tb = *reinterpret_cast<const float4*>(mp_b + n0);
#pragma unroll
    for (int k = 0; k < 14; k++) {
        float  a = ip[k];
        float4 w = sw4[k * 32 + nb];
        tb.x += a * w.x; tb.y += a * w.y; tb.z += a * w.z; tb.w += a * w.w;
    }

    float ts[5][4], td[5][4];
#pragma unroll
    for (int n = 0; n < 5; n++)
#pragma unroll
        for (int c = 0; c < 4; c++) { ts[n][c] = 0.0f; td[n][c] = 0.0f; }

#pragma unroll
    for (int k = 0; k < 15; k++) {
        float4 ws = sw4[(16 + k) * 32 + nb];
        float4 wd = sw4[(31 + k) * 32 + nb];
#pragma unroll
        for (int n = 0; n < 5; n++) {
            float a = ip[54 + n * 15 + k];
            ts[n][0] += a * ws.x; ts[n][1] += a * ws.y;
            ts[n][2] += a * ws.z; ts[n][3] += a * ws.w;
            td[n][0] += a * wd.x; td[n][1] += a * wd.y;
            td[n][2] += a * wd.z; td[n][3] += a * wd.w;
        }
    }

    const float4 w14 = sw4[14 * 32 + nb];
    const float4 w15 = sw4[15 * 32 + nb];

    float acc[5][4];
#pragma unroll
    for (int i = 0; i < 5; i++)
#pragma unroll
        for (int c = 0; c < 4; c++) acc[i][c] = 0.0f;

#pragma unroll
    for (int e = 0; e < 20; e++) {
        const int src = e >> 2, rr = e & 3;
        const int dst = (rr < src) ? rr : rr + 1;
        float d0 = ip[14 + e * 2];
        float d1 = ip[15 + e * 2];
        float v0 = tb.x + ts[src][0] + td[dst][0] + d0 * w14.x + d1 * w15.x;
        float v1 = tb.y + ts[src][1] + td[dst][1] + d0 * w14.y + d1 * w15.y;
        float v2 = tb.z + ts[src][2] + td[dst][2] + d0 * w14.z + d1 * w15.z;
        float v3 = tb.w + ts[src][3] + td[dst][3] + d0 * w14.w + d1 * w15.w;
        acc[dst][0] += fmaxf(v0, 0.0f);
        acc[dst][1] += fmaxf(v1, 0.0f);
        acc[dst][2] += fmaxf(v2, 0.0f);
        acc[dst][3] += fmaxf(v3, 0.0f);
    }

    const int b = b0 + bl;
#pragma unroll
    for (int i = 0; i < 5; i++) {
        size_t base = (size_t)(b * 5 + i) * 192 + 29 + n0;
#pragma unroll
        for (int c = 0; c < 4; c++)
            g_inp[base + c] = __float2half_rn(acc[i][c]);
    }

    // fused prep: cols 0..28 + zero 157..191, straight from sinp
    for (int idx = t; idx < 8 * 5 * 64; idx += 256) {
        int rl = idx >> 6;
        int c  = idx & 63;
        int bl2 = rl / 5;
        int n   = rl - bl2 * 5;
        const float* ip2 = sinp + bl2 * 132;
        float v; int col;
        if (c < 4)       { v = ip2[10 + c];                 col = c; }
        else if (c < 14) { v = ip2[c - 4];                  col = c; }
        else if (c < 29) { v = ip2[54 + n * 15 + (c - 14)]; col = c; }
        else             { v = 0.0f;                         col = 128 + c; } // 157..191
        size_t off = (size_t)((b0 + bl2) * 5 + n) * 192 + col;
        g_inp[off] = __float2half_rn(v);
    }
}

// ---------------------------------------------------------------------------
// K-wconv (+ fused out init): transpose weights to fp16, pad w1t K to 192.
// ---------------------------------------------------------------------------
__global__ void k_wconv(const float* __restrict__ w1, const float* __restrict__ w3,
                        const float* __restrict__ w2, const float* __restrict__ w4,
                        float* __restrict__ out,
                        const float* __restrict__ rb1, const float* __restrict__ rb2,
                        int B)
{
    int idx = blockIdx.x * 256 + threadIdx.x;
    const int N1 = 512 * 192;
    const int N2 = 512 * 256;
    if (idx < N1) {
        int n = idx / 192, k = idx - n * 192;
        float v = 0.0f;
        if (k < 157) v = (n < 256) ? w1[k * 256 + n] : w3[k * 256 + (n - 256)];
        g_w1t[idx] = __float2half_rn(v);
    } else if (idx < N1 + N2) {
        int j = idx - N1;
        int n = j / 256, k = j - n * 256;
        float v = (n < 256) ? w2[k * 256 + n] : w4[k * 256 + (n - 256)];
        g_w2t[j] = __float2half_rn(v);
    }
    if (idx < B) { out[idx] = rb1[0]; out[B + idx] = rb2[0]; }
}

// ---------------------------------------------------------------------------
// Pipeline layout: bias 0..512, rho 512..1024, s_arr 1024..1536,
// 2 buffers x { A, B } each 128x144B = 18432B. Total 75264; 2 CTAs/SM.
// Warp layout: 2(M) x 4(N); warp tile m64 x n32. K-chunk = 64 (4 ksteps).
// ---------------------------------------------------------------------------
#define PP_BIAS  0
#define PP_RHO   512
#define PP_SARR  1024
#define PP_BUF   1536
#define PP_TILE  18432
#define PP_BUFSZ (2 * PP_TILE)           // 36864
#define PP_SMEM  (PP_BUF + 2 * PP_BUFSZ) // 75264

// single-term fp16 compute, 2Mx4N, 4 ksteps: D += A*B
#define CHUNK_COMPUTE(bb)                                                       \
    do {                                                                        \
        const uint32_t base_ = sbase + PP_BUF + (bb) * PP_BUFSZ;                \
        _Pragma("unroll")                                                       \
        for (int ks = 0; ks < 4; ks++) {                                        \
            const uint32_t a_off = (uint32_t)(a_row * 144 + (ks * 16 + a_ksub) * 2); \
            const uint32_t b_off = (uint32_t)(b_row * 144 + (ks * 16 + b_ksub) * 2); \
            uint32_t af[4][4];                                                  \
            _Pragma("unroll")                                                   \
            for (int mt = 0; mt < 4; mt++)                                      \
                LDSM_X4(af[mt][0], af[mt][1], af[mt][2], af[mt][3],             \
                        base_ + a_off + mt * 16 * 144);                         \
            _Pragma("unroll")                                                   \
            for (int p = 0; p < 2; p++) {                                       \
                uint32_t bh[4];                                                 \
                LDSM_X4(bh[0], bh[1], bh[2], bh[3],                             \
                        base_ + PP_TILE + b_off + p * 16 * 144);                \
                _Pragma("unroll")                                               \
                for (int mt = 0; mt < 4; mt++)                                  \
                    _Pragma("unroll")                                           \
                    for (int hh = 0; hh < 2; hh++)                              \
                        mma16816(acc[mt][p * 2 + hh], af[mt], &bh[hh * 2]);     \
            }                                                                   \
        }                                                                       \
    } while (0)

#define STAGE_CHUNK(bb, kc)                                                     \
    do {                                                                        \
        uint32_t sd_ = sbase + PP_BUF + (bb) * PP_BUFSZ;                        \
        stage128x64_t256(sd_,            A_src + (kc) * 64, a_stride, t);       \
        stage128x64_t256(sd_ + PP_TILE,  B_src + (kc) * 64, b_stride, t);       \
        CP_COMMIT();                                                            \
    } while (0)

// ---------------------------------------------------------------------------
// K-phi1 (MMA, fp16, pipelined, chunk 64): K=192 (padded), 3 chunks.
// grid (4 nc, nrows/128): nc-CTAs sharing an A-tile are launch-adjacent (L2).
// ---------------------------------------------------------------------------
__global__ __launch_bounds__(256, 2) void k_phi1_mma(
    const float* __restrict__ phi_b1, const float* __restrict__ phi_b3)
{
    extern __shared__ char smemc[];
    const uint32_t sbase = smem_u32(smemc);
    const int t    = threadIdx.x;
    const int wid  = t >> 5;
    const int lane = t & 31;
    const int nc   = blockIdx.x;            // which 128 of N=512
    const int m0   = blockIdx.y * 128;

    float* sb = reinterpret_cast<float*>(smemc + PP_BIAS);
    if (t < 128) {
        int n = nc * 128 + t;
        sb[t] = (n < 256) ? phi_b1[n] : phi_b3[n - 256];
    }

    const __half* A_src = g_inp + (size_t)m0 * 192;
    const __half* B_src = g_w1t + (size_t)(nc * 128) * 192;
    const int a_stride = 192, b_stride = 192;

    const int warp_m = wid & 1;    // 2 x 64 rows
    const int warp_n = wid >> 1;   // 4 x 32 cols

    float acc[4][4][4];
#pragma unroll
    for (int mt = 0; mt < 4; mt++)
#pragma unroll
        for (int nt = 0; nt < 4; nt++)
#pragma unroll
            for (int j = 0; j < 4; j++) acc[mt][nt][j] = 0.0f;

    const int a_row  = warp_m * 64 + (lane & 15);
    const int a_ksub = (lane >> 4) * 8;
    const int b_row  = warp_n * 32 + (lane & 7) + ((lane >> 4) & 1) * 8;
    const int b_ksub = ((lane >> 3) & 1) * 8;

    STAGE_CHUNK(0, 0);
#pragma unroll
    for (int kc = 0; kc < 3; kc++) {
        if (kc < 2) {
            STAGE_CHUNK((kc + 1) & 1, kc + 1);
            CP_WAIT(1);
        } else {
            CP_WAIT(0);
        }
        __syncthreads();
        CHUNK_COMPUTE(kc & 1);
        __syncthreads();
    }

    // epilogue: relu(+bias) -> g_h (fp16)
#pragma unroll
    for (int mt = 0; mt < 4; mt++)
#pragma unroll
        for (int nt = 0; nt < 4; nt++) {
            int c = warp_n * 32 + nt * 8 + (lane & 3) * 2;
            float b0 = sb[c], b1 = sb[c + 1];
#pragma unroll
            for (int half_i = 0; half_i < 2; half_i++) {
                int row = warp_m * 64 + mt * 16 + (lane >> 2) + half_i * 8;
                float v0 = fmaxf(acc[mt][nt][half_i * 2]     + b0, 0.0f);
                float v1 = fmaxf(acc[mt][nt][half_i * 2 + 1] + b1, 0.0f);
                __half h0 = __float2half_rn(v0);
                __half h1 = __float2half_rn(v1);
                uint32_t ph = ((uint32_t)__half_as_ushort(h1) << 16) | __half_as_ushort(h0);
                size_t off = (size_t)(m0 + row) * 512 + nc * 128 + c;
                *reinterpret_cast<uint32_t*>(g_h + off) = ph;
            }
        }
}

// ---------------------------------------------------------------------------
// K-phi2 (MMA, fp16, pipelined, chunk 64): K=256, 4 chunks.
// grid (4, nrows/128): x = br*2+nc -> A-tile-sharing pair launch-adjacent (L2).
// ---------------------------------------------------------------------------
__global__ __launch_bounds__(256, 2) void k_phi2_mma(
    const float* __restrict__ phi_b2, const float* __restrict__ phi_b4,
    const float* __restrict__ rho_w1, const float* __restrict__ rho_w2,
    float* __restrict__ out, int B)
{
    extern __shared__ char smemc[];
    const uint32_t sbase = smem_u32(smemc);
    const int t    = threadIdx.x;
    const int wid  = t >> 5;
    const int lane = t & 31;
    const int br   = blockIdx.x >> 1;
    const int nc   = blockIdx.x & 1;
    const int m0   = blockIdx.y * 128;

    const float* bias = br ? phi_b4 : phi_b2;
    const float* rho  = br ? rho_w2 : rho_w1;

    float* sb    = reinterpret_cast<float*>(smemc + PP_BIAS);
    float* sr    = reinterpret_cast<float*>(smemc + PP_RHO);
    float* s_arr = reinterpret_cast<float*>(smemc + PP_SARR);

    if (t < 128) {
        sb[t] = bias[nc * 128 + t];
        sr[t] = rho[nc * 128 + t];
        s_arr[t] = 0.0f;
    }

    const __half* A_src = g_h + (size_t)m0 * 512 + br * 256;
    const __half* B_src = g_w2t + (size_t)(br * 256 + nc * 128) * 256;
    const int a_stride = 512, b_stride = 256;

    const int warp_m = wid & 1;    // 2 x 64 rows
    const int warp_n = wid >> 1;   // 4 x 32 cols

    float acc[4][4][4];
#pragma unroll
    for (int mt = 0; mt < 4; mt++)
#pragma unroll
        for (int nt = 0; nt < 4; nt++)
#pragma unroll
            for (int j = 0; j < 4; j++) acc[mt][nt][j] = 0.0f;

    const int a_row  = warp_m * 64 + (lane & 15);
    const int a_ksub = (lane >> 4) * 8;
    const int b_row  = warp_n * 32 + (lane & 7) + ((lane >> 4) & 1) * 8;
    const int b_ksub = ((lane >> 3) & 1) * 8;

    STAGE_CHUNK(0, 0);
#pragma unroll
    for (int kc = 0; kc < 4; kc++) {
        if (kc < 3) {
            STAGE_CHUNK((kc + 1) & 1, kc + 1);
            CP_WAIT(1);
        } else {
            CP_WAIT(0);
        }
        __syncthreads();
        CHUNK_COMPUTE(kc & 1);
        __syncthreads();
    }

    // epilogue: relu(+bias)*rho, reduce cols, per-row sums, per-b atomics
#pragma unroll
    for (int mt = 0; mt < 4; mt++) {
        float s0 = 0.0f, s1 = 0.0f;
#pragma unroll
        for (int nt = 0; nt < 4; nt++) {
            int c = warp_n * 32 + nt * 8 + (lane & 3) * 2;
            float b0v = sb[c], b1v = sb[c + 1];
            float r0v = sr[c], r1v = sr[c + 1];
            s0 += fmaxf(acc[mt][nt][0] + b0v, 0.0f) * r0v;
            s0 += fmaxf(acc[mt][nt][1] + b1v, 0.0f) * r1v;
            s1 += fmaxf(acc[mt][nt][2] + b0v, 0.0f) * r0v;
            s1 += fmaxf(acc[mt][nt][3] + b1v, 0.0f) * r1v;
        }
        s0 += __shfl_xor_sync(0xffffffffu, s0, 1);
        s0 += __shfl_xor_sync(0xffffffffu, s0, 2);
        s1 += __shfl_xor_sync(0xffffffffu, s1, 1);
        s1 += __shfl_xor_sync(0xffffffffu, s1, 2);
        if ((lane & 3) == 0) {
            int row = warp_m * 64 + mt * 16 + (lane >> 2);
            atomicAdd(&s_arr[row], s0);
            atomicAdd(&s_arr[row + 8], s1);
        }
    }
    __syncthreads();

    {
        int bfirst = m0 / 5;
        int blast  = (m0 + 127) / 5;
        int ng = blast - bfirst + 1;
        if (t < ng) {
            int b = bfirst + t;
            float s = 0.0f;
#pragma unroll
            for (int r = 0; r < 5; r++) {
                int m = b * 5 + r;
                if (m >= m0 && m < m0 + 128) s += s_arr[m - m0];
            }
            atomicAdd(&out[br * B + b], s);
        }
    }
}

// ---------------------------------------------------------------------------
extern "C" void kernel_launch(void* const* d_in, const int* in_sizes, int n_in,
                              void* d_out, int out_size)
{
    const float* obs    = (const float*)d_in[0];
    const float* act    = (const float*)d_in[1];
    const float* ag     = (const float*)d_in[2];
    const float* g      = (const float*)d_in[3];
    const float* mp_w   = (const float*)d_in[4];
    const float* mp_b   = (const float*)d_in[5];
    const float* phi_w1 = (const float*)d_in[6];
    const float* phi_b1 = (const float*)d_in[7];
    const float* phi_w2 = (const float*)d_in[8];
    const float* phi_b2 = (const float*)d_in[9];
    const float* phi_w3 = (const float*)d_in[10];
    const float* phi_b3 = (const float*)d_in[11];
    const float* phi_w4 = (const float*)d_in[12];
    const float* phi_b4 = (const float*)d_in[13];
    const float* rho_w1 = (const float*)d_in[14];
    const float* rho_b1 = (const float*)d_in[15];
    const float* rho_w2 = (const float*)d_in[16];
    const float* rho_b2 = (const float*)d_in[17];
    float* out = (float*)d_out;

    const int B = in_sizes[1] / 4;  // act is (B,4)
    const int nrows = B * 5;

    const int S1 = (46 * 128 + 8 * 132) * 4;   // 27,776 B
    cudaFuncSetAttribute(k_edge, cudaFuncAttributeMaxDynamicSharedMemorySize, S1);
    cudaFuncSetAttribute(k_phi1_mma, cudaFuncAttributeMaxDynamicSharedMemorySize, PP_SMEM);
    cudaFuncSetAttribute(k_phi2_mma, cudaFuncAttributeMaxDynamicSharedMemorySize, PP_SMEM);

    k_wconv<<<(512 * 192 + 512 * 256 + 255) / 256, 256>>>(
        phi_w1, phi_w3, phi_w2, phi_w4, out, rho_b1, rho_b2, B);
    k_edge<<<B / 8, 256, S1>>>(obs, act, ag, g, mp_w, mp_b);
    k_phi1_mma<<<dim3(4, nrows / 128), 256, PP_SMEM>>>(phi_b1, phi_b3);
    k_phi2_mma<<<dim3(4, nrows / 128), 256, PP_SMEM>>>(
        phi_b2, phi_b4, rho_w1, rho_w2, out, B);
}